// round 9
// baseline (speedup 1.0000x reference)
#include <cuda_runtime.h>
#include <cuda_bf16.h>
#include <cstdint>

// ---------------- problem constants ----------------
#define T_    4
#define NBN   65536
#define P_    63
#define D_    128
#define M_    262144
#define TBND  8388608
#define NBLK  2048              // GEMM blocks (128 rows each)

// dyn smem: A limbs [0,16K,32K), B limbs [49152, 65536, 81920). Stage reuses [0,67584).
#define SM_GEMM 98304

// ---------------- device globals ----------------
__device__ float g_h[(size_t)M_ * D_];                 // 134 MB intermediate
__device__ __align__(16) unsigned char g_wb[49152];    // 3 pre-swizzled W bf16 limb tiles
__device__ float g_psum[NBLK * D_];
__device__ float g_psq [NBLK * D_];
__device__ float g_mean[D_];
__device__ float g_rstd[D_];

// ---------------- helpers ----------------
__device__ __forceinline__ uint32_t smem_u32(const void* p){
    uint32_t a;
    asm("{ .reg .u64 t; cvta.to.shared.u64 t, %1; cvt.u32.u64 %0, t; }" : "=r"(a) : "l"(p));
    return a;
}
__device__ __forceinline__ void ldsm4(uint32_t* r, uint32_t addr){
    asm volatile("ldmatrix.sync.aligned.m8n8.x4.shared.b16 {%0,%1,%2,%3}, [%4];"
        : "=r"(r[0]), "=r"(r[1]), "=r"(r[2]), "=r"(r[3]) : "r"(addr));
}
__device__ __forceinline__ void mma16816(float* c, const uint32_t* a, const uint32_t* b){
    asm volatile("mma.sync.aligned.m16n8k16.row.col.f32.bf16.bf16.f32 "
        "{%0,%1,%2,%3}, {%4,%5,%6,%7}, {%8,%9}, {%0,%1,%2,%3};"
        : "+f"(c[0]), "+f"(c[1]), "+f"(c[2]), "+f"(c[3])
        : "r"(a[0]), "r"(a[1]), "r"(a[2]), "r"(a[3]), "r"(b[0]), "r"(b[1]));
}
// full 16-mma sweep of one A limb against one B fragment set (order == R8)
__device__ __forceinline__ void sweep(float acc[2][8][4],
                                      const uint32_t A[2][4], const uint32_t B[4][4]){
    #pragma unroll
    for (int rg = 0; rg < 2; rg++)
        #pragma unroll
        for (int j = 0; j < 4; j++){
            mma16816(acc[rg][2*j],   A[rg], &B[j][0]);
            mma16816(acc[rg][2*j+1], A[rg], &B[j][2]);
        }
}
// swizzled byte offset inside a [128 rows x 64 bf16] tile (identical to R3/R8)
__device__ __forceinline__ uint32_t sw_off(int row, int k){
    return (uint32_t)(row * 128 + ((((k >> 3) ^ row) & 7) << 4) + ((k & 7) << 1));
}

// ---------------- K0: W -> 3 pre-swizzled bf16 limb tiles (verbatim) --------
__global__ __launch_bounds__(256) void k_wt(const float* __restrict__ W){
    int idx = blockIdx.x * 256 + threadIdx.x;
    if (idx >= D_ * 64) return;
    int d = idx >> 6;
    int k = idx & 63;
    float w = (k < P_) ? W[d * P_ + k] : 0.f;
    __nv_bfloat16 w0 = __float2bfloat16(w);
    float r1 = w - __bfloat162float(w0);
    __nv_bfloat16 w1 = __float2bfloat16(r1);
    float r2 = r1 - __bfloat162float(w1);
    __nv_bfloat16 w2 = __float2bfloat16(r2);
    uint32_t off = sw_off(d, k);
    *(__nv_bfloat16*)(g_wb + off)         = w0;
    *(__nv_bfloat16*)(g_wb + 16384 + off) = w1;
    *(__nv_bfloat16*)(g_wb + 32768 + off) = w2;
}

// ---------------- K1: 6-product split-bf16 HMMA GEMM (math == R8, pipelined) -
__global__ __launch_bounds__(256, 2) void k_gemm(const float* __restrict__ x){
    extern __shared__ __align__(1024) unsigned char smem[];
    const uint32_t sb = smem_u32(smem);
    const int tid = threadIdx.x;
    const int w   = tid >> 5;
    const int l   = tid & 31;
    const int blk = blockIdx.x;

    // B limbs: 48KB copy of pre-swizzled tiles
    {
        uint4* bs = (uint4*)(smem + 49152);
        const uint4* gs = (const uint4*)g_wb;
        #pragma unroll
        for (int i = 0; i < 12; i++) bs[tid + i * 256] = gs[tid + i * 256];
    }
    // A limbs: 2 threads per row, packed bf16x2 3-limb split (verbatim R8)
    {
        const float* xg = x + (size_t)blk * (128 * P_);
        const int row  = tid >> 1;
        const int half = tid & 1;
        const float* xr = xg + row * P_;
        #pragma unroll
        for (int i = 0; i < 16; i++){
            int p = half * 16 + i;
            int k = p * 2;
            float v0 = xr[k];
            float v1 = (k + 1 < P_) ? xr[k + 1] : 0.f;
            uint32_t p0;
            asm("cvt.rn.bf16x2.f32 %0, %1, %2;" : "=r"(p0) : "f"(v1), "f"(v0));
            float f0 = __uint_as_float(p0 << 16);
            float f1 = __uint_as_float(p0 & 0xffff0000u);
            float r0 = v0 - f0, r1 = v1 - f1;
            uint32_t p1;
            asm("cvt.rn.bf16x2.f32 %0, %1, %2;" : "=r"(p1) : "f"(r1), "f"(r0));
            float g0 = __uint_as_float(p1 << 16);
            float g1 = __uint_as_float(p1 & 0xffff0000u);
            float s0 = r0 - g0, s1 = r1 - g1;
            uint32_t p2;
            asm("cvt.rn.bf16x2.f32 %0, %1, %2;" : "=r"(p2) : "f"(s1), "f"(s0));
            uint32_t off = (uint32_t)(row * 128
                         + ((((k >> 3) ^ row) & 7) << 4) + ((k & 7) << 1));
            *(uint32_t*)(smem + off)         = p0;
            *(uint32_t*)(smem + 16384 + off) = p1;
            *(uint32_t*)(smem + 32768 + off) = p2;
        }
    }
    __syncthreads();

    // warp tile: 32 rows x 64 cols. 8 warps = 4 row-groups x 2 col-groups.
    const int rowg = (w >> 1) * 32;
    const int colg = (w & 1) * 64;
    const int a_r  = l & 15;
    const int a_kb = l >> 4;
    const int b_rl = (l & 7) + ((l >> 4) & 1) * 8;
    const int b_kb = (l >> 3) & 1;

    // per-lane base addresses; per-ks address = base ^ (ks<<5)
    uint32_t aBase[2];
    #pragma unroll
    for (int rg = 0; rg < 2; rg++){
        int row = rowg + rg * 16 + a_r;
        aBase[rg] = sb + (uint32_t)row * 128
                  + (uint32_t)(((a_kb ^ (row & 7)) & 7) << 4);
    }
    uint32_t bBase[4];
    #pragma unroll
    for (int j = 0; j < 4; j++){
        int rowd = colg + j * 16 + b_rl;
        bBase[j] = sb + 49152 + (uint32_t)rowd * 128
                 + (uint32_t)(((b_kb ^ (rowd & 7)) & 7) << 4);
    }

    float acc[2][8][4];
    #pragma unroll
    for (int i = 0; i < 2; i++)
        #pragma unroll
        for (int j = 0; j < 8; j++)
            #pragma unroll
            for (int e = 0; e < 4; e++) acc[i][j][e] = 0.f;

    uint32_t A0[2][4], A1[2][4], A2[2][4], Bx[4][4], By[4][4];

    // per-acc product order: (0,0),(1,0),(2,0),(0,1),(1,1),(0,2); ks ascending
    #pragma unroll
    for (int ks = 0; ks < 4; ks++){
        const uint32_t kx = (uint32_t)(ks << 5);
        #pragma unroll
        for (int rg = 0; rg < 2; rg++){
            uint32_t a = aBase[rg] ^ kx;
            ldsm4(A0[rg], a);
            ldsm4(A1[rg], a + 16384);
            ldsm4(A2[rg], a + 32768);
        }
        #pragma unroll
        for (int j = 0; j < 4; j++) ldsm4(Bx[j], bBase[j] ^ kx);   // B limb 0

        // sweep A0 x B0 (rg0) with B1 prefetch interleaved into By
        mma16816(acc[0][0], A0[0], &Bx[0][0]); mma16816(acc[0][1], A0[0], &Bx[0][2]);
        ldsm4(By[0], (bBase[0] ^ kx) + 16384);
        mma16816(acc[0][2], A0[0], &Bx[1][0]); mma16816(acc[0][3], A0[0], &Bx[1][2]);
        ldsm4(By[1], (bBase[1] ^ kx) + 16384);
        mma16816(acc[0][4], A0[0], &Bx[2][0]); mma16816(acc[0][5], A0[0], &Bx[2][2]);
        ldsm4(By[2], (bBase[2] ^ kx) + 16384);
        mma16816(acc[0][6], A0[0], &Bx[3][0]); mma16816(acc[0][7], A0[0], &Bx[3][2]);
        ldsm4(By[3], (bBase[3] ^ kx) + 16384);
        // rg1 of A0 x B0
        #pragma unroll
        for (int j = 0; j < 4; j++){
            mma16816(acc[1][2*j],   A0[1], &Bx[j][0]);
            mma16816(acc[1][2*j+1], A0[1], &Bx[j][2]);
        }
        sweep(acc, A1, Bx);            // (1,0)
        sweep(acc, A2, Bx);            // (2,0) -- last use of B0 buffer
        #pragma unroll
        for (int j = 0; j < 4; j++) ldsm4(Bx[j], (bBase[j] ^ kx) + 32768);  // B limb 2
        sweep(acc, A0, By);            // (0,1)
        sweep(acc, A1, By);            // (1,1)
        sweep(acc, A0, Bx);            // (0,2)
    }

    // ---- epilogue: stage (verbatim R8), coalesced h write, stats ----
    __syncthreads();
    float* stg = (float*)smem;                 // [128][132]
    #pragma unroll
    for (int rg = 0; rg < 2; rg++){
        int rr = rowg + rg * 16 + (l >> 2);
        #pragma unroll
        for (int jh = 0; jh < 8; jh++){
            int col = colg + jh * 8 + (l & 3) * 2;
            *(float2*)(stg + rr * 132 + col)       = make_float2(acc[rg][jh][0], acc[rg][jh][1]);
            *(float2*)(stg + (rr + 8) * 132 + col) = make_float2(acc[rg][jh][2], acc[rg][jh][3]);
        }
    }
    __syncthreads();

    float* hg = g_h + (size_t)blk * (128 * 128);
    #pragma unroll
    for (int j = 0; j < 16; j++){
        int idx = tid + j * 256;
        int row = idx >> 5;
        int c4  = idx & 31;
        float4 v = *(const float4*)(stg + row * 132 + c4 * 4);
        *(float4*)(hg + row * 128 + c4 * 4) = v;
    }
    if (tid < 128){
        float s = 0.f;
        #pragma unroll 8
        for (int r = 0; r < 128; r++) s += stg[r * 132 + tid];
        g_psum[blk * D_ + tid] = s;
    } else {
        int d = tid - 128;
        float q = 0.f;
        #pragma unroll 8
        for (int r = 0; r < 128; r++){ float v = stg[r * 132 + d]; q += v * v; }
        g_psq[blk * D_ + d] = q;
    }
}

// ---------------- K2: finalize stats (verbatim R8) ----------------
__global__ __launch_bounds__(256) void k_stats(const float* __restrict__ gamma,
                                               const float* __restrict__ beta){
    __shared__ double ss[256];
    __shared__ double sq[256];
    const int d = blockIdx.x;
    const int t = threadIdx.x;
    double s = 0.0, q = 0.0;
    for (int b = t; b < NBLK; b += 256){
        s += (double)g_psum[b * D_ + d];
        q += (double)g_psq [b * D_ + d];
    }
    ss[t] = s; sq[t] = q;
    __syncthreads();
    for (int o = 128; o > 0; o >>= 1){
        if (t < o){ ss[t] += ss[t + o]; sq[t] += sq[t + o]; }
        __syncthreads();
    }
    if (t == 0){
        double mean = ss[0] / (double)M_;
        double ex2  = sq[0] / (double)M_;
        float meanf = (float)mean;
        float varf  = (float)(ex2 - mean * mean);
        float rstd  = (float)(1.0 / sqrt((double)(varf + 1e-5f)));
        float gm = gamma[d], bt = beta[d];
        float rs = rstd * gm;
        float mn = (rs != 0.f) ? (meanf - bt / rs) : meanf;
        g_mean[d] = mn;
        g_rstd[d] = rs;
    }
}

// ---------------- K3: BN + 4-step LIF, 8 floats/thread (same per-elem math) -
__global__ __launch_bounds__(256) void k_lif(float* __restrict__ out){
    int i = blockIdx.x * 256 + threadIdx.x;        // 0 .. 1048575
    size_t base = (size_t)i << 3;                  // 8 consecutive channels
    int d0 = (int)(base & 127);
    float4 mnA = *(const float4*)(g_mean + d0);
    float4 rsA = *(const float4*)(g_rstd + d0);
    float4 mnB = *(const float4*)(g_mean + d0 + 4);
    float4 rsB = *(const float4*)(g_rstd + d0 + 4);

    float va[4] = {0.f, 0.f, 0.f, 0.f};
    float vb[4] = {0.f, 0.f, 0.f, 0.f};
    #pragma unroll
    for (int t = 0; t < 4; t++){
        const float* hp = g_h + base + (size_t)t * TBND;
        float4 hA = *(const float4*)(hp);
        float4 hB = *(const float4*)(hp + 4);
        float4 oA, oB;
        #pragma unroll
        for (int e = 0; e < 4; e++){
            float n = (((const float*)&hA)[e] - ((const float*)&mnA)[e]) * ((const float*)&rsA)[e];
            va[e] = va[e] + (n - va[e]) * 0.5f;
            ((float*)&oA)[e] = (va[e] >= 1.0f) ? 1.0f : 0.0f;
            if (va[e] >= 1.0f) va[e] = 0.f;
        }
        #pragma unroll
        for (int e = 0; e < 4; e++){
            float n = (((const float*)&hB)[e] - ((const float*)&mnB)[e]) * ((const float*)&rsB)[e];
            vb[e] = vb[e] + (n - vb[e]) * 0.5f;
            ((float*)&oB)[e] = (vb[e] >= 1.0f) ? 1.0f : 0.0f;
            if (vb[e] >= 1.0f) vb[e] = 0.f;
        }
        float* op = out + base + (size_t)t * TBND;
        *(float4*)(op)     = oA;
        *(float4*)(op + 4) = oB;
    }
}

// ---------------- launch ----------------
extern "C" void kernel_launch(void* const* d_in, const int* in_sizes, int n_in,
                              void* d_out, int out_size){
    const float* x     = (const float*)d_in[0];
    const float* W     = (const float*)d_in[1];
    const float* gamma = (const float*)d_in[2];
    const float* beta  = (const float*)d_in[3];
    float* out = (float*)d_out;

    cudaFuncSetAttribute(k_gemm, cudaFuncAttributeMaxDynamicSharedMemorySize, SM_GEMM);

    k_wt   <<<32, 256>>>(W);
    k_gemm <<<NBLK, 256, SM_GEMM>>>(x);
    k_stats<<<D_, 256>>>(gamma, beta);
    k_lif  <<<TBND / 8 / 256, 256>>>(out);
}

// round 10
// speedup vs baseline: 1.0854x; 1.0854x over previous
#include <cuda_runtime.h>
#include <cuda_bf16.h>
#include <cstdint>

// ---------------- problem constants ----------------
#define T_    4
#define NBN   65536
#define P_    63
#define D_    128
#define M_    262144
#define TBND  8388608
#define NBLK  2048              // GEMM blocks (128 rows each)

// dyn smem: A limbs [0,16K,32K), B limbs [49152, 65536, 81920).
// x raw stage reuses B area [49152, +32256). Epilogue stage reuses [0,67584).
#define SM_GEMM 98304

// ---------------- device globals ----------------
__device__ float g_h[(size_t)M_ * D_];                 // 134 MB intermediate
__device__ __align__(16) unsigned char g_wb[49152];    // 3 pre-swizzled W bf16 limb tiles
__device__ float g_psum[NBLK * D_];
__device__ float g_psq [NBLK * D_];
__device__ float g_mean[D_];
__device__ float g_rstd[D_];

// ---------------- helpers ----------------
__device__ __forceinline__ uint32_t smem_u32(const void* p){
    uint32_t a;
    asm("{ .reg .u64 t; cvta.to.shared.u64 t, %1; cvt.u32.u64 %0, t; }" : "=r"(a) : "l"(p));
    return a;
}
__device__ __forceinline__ void ldsm4(uint32_t* r, uint32_t addr){
    asm volatile("ldmatrix.sync.aligned.m8n8.x4.shared.b16 {%0,%1,%2,%3}, [%4];"
        : "=r"(r[0]), "=r"(r[1]), "=r"(r[2]), "=r"(r[3]) : "r"(addr));
}
__device__ __forceinline__ void mma16816(float* c, const uint32_t* a, const uint32_t* b){
    asm volatile("mma.sync.aligned.m16n8k16.row.col.f32.bf16.bf16.f32 "
        "{%0,%1,%2,%3}, {%4,%5,%6,%7}, {%8,%9}, {%0,%1,%2,%3};"
        : "+f"(c[0]), "+f"(c[1]), "+f"(c[2]), "+f"(c[3])
        : "r"(a[0]), "r"(a[1]), "r"(a[2]), "r"(a[3]), "r"(b[0]), "r"(b[1]));
}
// full 16-mma sweep of one A limb against one B fragment set (order == R8)
__device__ __forceinline__ void sweep(float acc[2][8][4],
                                      const uint32_t A[2][4], const uint32_t B[4][4]){
    #pragma unroll
    for (int rg = 0; rg < 2; rg++)
        #pragma unroll
        for (int j = 0; j < 4; j++){
            mma16816(acc[rg][2*j],   A[rg], &B[j][0]);
            mma16816(acc[rg][2*j+1], A[rg], &B[j][2]);
        }
}
// swizzled byte offset inside a [128 rows x 64 bf16] tile (identical to R3/R8)
__device__ __forceinline__ uint32_t sw_off(int row, int k){
    return (uint32_t)(row * 128 + ((((k >> 3) ^ row) & 7) << 4) + ((k & 7) << 1));
}

// ---------------- K0: W -> 3 pre-swizzled bf16 limb tiles (verbatim) --------
__global__ __launch_bounds__(256) void k_wt(const float* __restrict__ W){
    int idx = blockIdx.x * 256 + threadIdx.x;
    if (idx >= D_ * 64) return;
    int d = idx >> 6;
    int k = idx & 63;
    float w = (k < P_) ? W[d * P_ + k] : 0.f;
    __nv_bfloat16 w0 = __float2bfloat16(w);
    float r1 = w - __bfloat162float(w0);
    __nv_bfloat16 w1 = __float2bfloat16(r1);
    float r2 = r1 - __bfloat162float(w1);
    __nv_bfloat16 w2 = __float2bfloat16(r2);
    uint32_t off = sw_off(d, k);
    *(__nv_bfloat16*)(g_wb + off)         = w0;
    *(__nv_bfloat16*)(g_wb + 16384 + off) = w1;
    *(__nv_bfloat16*)(g_wb + 32768 + off) = w2;
}

// ---------------- K1: 6-product split-bf16 HMMA GEMM (math == R8) -----------
__global__ __launch_bounds__(256, 2) void k_gemm(const float* __restrict__ x){
    extern __shared__ __align__(1024) unsigned char smem[];
    const uint32_t sb = smem_u32(smem);
    const int tid = threadIdx.x;
    const int w   = tid >> 5;
    const int l   = tid & 31;
    const int blk = blockIdx.x;

    // --- stage x raw: fully coalesced float4 loads into B area ---
    {
        float4* xs4 = (float4*)(smem + 49152);
        const float4* xg4 = (const float4*)(x + (size_t)blk * (128 * P_));
        #pragma unroll
        for (int i = 0; i < 8; i++){
            int idx = tid + i * 256;
            if (idx < 2016) xs4[idx] = xg4[idx];
        }
    }
    __syncthreads();

    // --- A limbs: identical split arithmetic, sourced from smem stage ---
    {
        const float* xs = (const float*)(smem + 49152);
        const int row  = tid >> 1;
        const int half = tid & 1;
        const float* xr = xs + row * P_;
        #pragma unroll
        for (int i = 0; i < 16; i++){
            int p = half * 16 + i;
            int k = p * 2;
            float v0 = xr[k];
            float v1 = (k + 1 < P_) ? xr[k + 1] : 0.f;
            uint32_t p0;
            asm("cvt.rn.bf16x2.f32 %0, %1, %2;" : "=r"(p0) : "f"(v1), "f"(v0));
            float f0 = __uint_as_float(p0 << 16);
            float f1 = __uint_as_float(p0 & 0xffff0000u);
            float r0 = v0 - f0, r1 = v1 - f1;
            uint32_t p1;
            asm("cvt.rn.bf16x2.f32 %0, %1, %2;" : "=r"(p1) : "f"(r1), "f"(r0));
            float g0 = __uint_as_float(p1 << 16);
            float g1 = __uint_as_float(p1 & 0xffff0000u);
            float s0 = r0 - g0, s1 = r1 - g1;
            uint32_t p2;
            asm("cvt.rn.bf16x2.f32 %0, %1, %2;" : "=r"(p2) : "f"(s1), "f"(s0));
            uint32_t off = (uint32_t)(row * 128
                         + ((((k >> 3) ^ row) & 7) << 4) + ((k & 7) << 1));
            *(uint32_t*)(smem + off)         = p0;
            *(uint32_t*)(smem + 16384 + off) = p1;
            *(uint32_t*)(smem + 32768 + off) = p2;
        }
    }
    __syncthreads();

    // --- B limbs: 48KB copy of pre-swizzled tiles (overwrites x stage) ---
    {
        uint4* bs = (uint4*)(smem + 49152);
        const uint4* gs = (const uint4*)g_wb;
        #pragma unroll
        for (int i = 0; i < 12; i++) bs[tid + i * 256] = gs[tid + i * 256];
    }
    __syncthreads();

    // warp tile: 32 rows x 64 cols. 8 warps = 4 row-groups x 2 col-groups.
    const int rowg = (w >> 1) * 32;
    const int colg = (w & 1) * 64;
    const int a_r  = l & 15;
    const int a_kb = l >> 4;
    const int b_rl = (l & 7) + ((l >> 4) & 1) * 8;
    const int b_kb = (l >> 3) & 1;

    // per-lane base addresses; per-ks address = base ^ (ks<<5)
    uint32_t aBase[2];
    #pragma unroll
    for (int rg = 0; rg < 2; rg++){
        int row = rowg + rg * 16 + a_r;
        aBase[rg] = sb + (uint32_t)row * 128
                  + (uint32_t)(((a_kb ^ (row & 7)) & 7) << 4);
    }
    uint32_t bBase[4];
    #pragma unroll
    for (int j = 0; j < 4; j++){
        int rowd = colg + j * 16 + b_rl;
        bBase[j] = sb + 49152 + (uint32_t)rowd * 128
                 + (uint32_t)(((b_kb ^ (rowd & 7)) & 7) << 4);
    }

    float acc[2][8][4];
    #pragma unroll
    for (int i = 0; i < 2; i++)
        #pragma unroll
        for (int j = 0; j < 8; j++)
            #pragma unroll
            for (int e = 0; e < 4; e++) acc[i][j][e] = 0.f;

    uint32_t A0[2][4], A1[2][4], A2[2][4], Bx[4][4], By[4][4];

    // per-acc product order: (0,0),(1,0),(2,0),(0,1),(1,1),(0,2); ks ascending
    #pragma unroll
    for (int ks = 0; ks < 4; ks++){
        const uint32_t kx = (uint32_t)(ks << 5);
        #pragma unroll
        for (int rg = 0; rg < 2; rg++){
            uint32_t a = aBase[rg] ^ kx;
            ldsm4(A0[rg], a);
            ldsm4(A1[rg], a + 16384);
            ldsm4(A2[rg], a + 32768);
        }
        #pragma unroll
        for (int j = 0; j < 4; j++) ldsm4(Bx[j], bBase[j] ^ kx);   // B limb 0

        // sweep A0 x B0 (rg0) with B1 prefetch interleaved into By
        mma16816(acc[0][0], A0[0], &Bx[0][0]); mma16816(acc[0][1], A0[0], &Bx[0][2]);
        ldsm4(By[0], (bBase[0] ^ kx) + 16384);
        mma16816(acc[0][2], A0[0], &Bx[1][0]); mma16816(acc[0][3], A0[0], &Bx[1][2]);
        ldsm4(By[1], (bBase[1] ^ kx) + 16384);
        mma16816(acc[0][4], A0[0], &Bx[2][0]); mma16816(acc[0][5], A0[0], &Bx[2][2]);
        ldsm4(By[2], (bBase[2] ^ kx) + 16384);
        mma16816(acc[0][6], A0[0], &Bx[3][0]); mma16816(acc[0][7], A0[0], &Bx[3][2]);
        ldsm4(By[3], (bBase[3] ^ kx) + 16384);
        // rg1 of A0 x B0
        #pragma unroll
        for (int j = 0; j < 4; j++){
            mma16816(acc[1][2*j],   A0[1], &Bx[j][0]);
            mma16816(acc[1][2*j+1], A0[1], &Bx[j][2]);
        }
        sweep(acc, A1, Bx);            // (1,0)
        sweep(acc, A2, Bx);            // (2,0) -- last use of B0 buffer
        #pragma unroll
        for (int j = 0; j < 4; j++) ldsm4(Bx[j], (bBase[j] ^ kx) + 32768);  // B limb 2
        sweep(acc, A0, By);            // (0,1)
        sweep(acc, A1, By);            // (1,1)
        sweep(acc, A0, Bx);            // (0,2)
    }

    // ---- epilogue: stage (verbatim R8), coalesced h write, stats ----
    __syncthreads();
    float* stg = (float*)smem;                 // [128][132]
    #pragma unroll
    for (int rg = 0; rg < 2; rg++){
        int rr = rowg + rg * 16 + (l >> 2);
        #pragma unroll
        for (int jh = 0; jh < 8; jh++){
            int col = colg + jh * 8 + (l & 3) * 2;
            *(float2*)(stg + rr * 132 + col)       = make_float2(acc[rg][jh][0], acc[rg][jh][1]);
            *(float2*)(stg + (rr + 8) * 132 + col) = make_float2(acc[rg][jh][2], acc[rg][jh][3]);
        }
    }
    __syncthreads();

    float* hg = g_h + (size_t)blk * (128 * 128);
    #pragma unroll
    for (int j = 0; j < 16; j++){
        int idx = tid + j * 256;
        int row = idx >> 5;
        int c4  = idx & 31;
        float4 v = *(const float4*)(stg + row * 132 + c4 * 4);
        *(float4*)(hg + row * 128 + c4 * 4) = v;
    }
    if (tid < 128){
        float s = 0.f;
        #pragma unroll 8
        for (int r = 0; r < 128; r++) s += stg[r * 132 + tid];
        g_psum[blk * D_ + tid] = s;
    } else {
        int d = tid - 128;
        float q = 0.f;
        #pragma unroll 8
        for (int r = 0; r < 128; r++){ float v = stg[r * 132 + d]; q += v * v; }
        g_psq[blk * D_ + d] = q;
    }
}

// ---------------- K2: finalize stats (verbatim R8) ----------------
__global__ __launch_bounds__(256) void k_stats(const float* __restrict__ gamma,
                                               const float* __restrict__ beta){
    __shared__ double ss[256];
    __shared__ double sq[256];
    const int d = blockIdx.x;
    const int t = threadIdx.x;
    double s = 0.0, q = 0.0;
    for (int b = t; b < NBLK; b += 256){
        s += (double)g_psum[b * D_ + d];
        q += (double)g_psq [b * D_ + d];
    }
    ss[t] = s; sq[t] = q;
    __syncthreads();
    for (int o = 128; o > 0; o >>= 1){
        if (t < o){ ss[t] += ss[t + o]; sq[t] += sq[t + o]; }
        __syncthreads();
    }
    if (t == 0){
        double mean = ss[0] / (double)M_;
        double ex2  = sq[0] / (double)M_;
        float meanf = (float)mean;
        float varf  = (float)(ex2 - mean * mean);
        float rstd  = (float)(1.0 / sqrt((double)(varf + 1e-5f)));
        float gm = gamma[d], bt = beta[d];
        float rs = rstd * gm;
        float mn = (rs != 0.f) ? (meanf - bt / rs) : meanf;
        g_mean[d] = mn;
        g_rstd[d] = rs;
    }
}

// ---------------- K3: BN + 4-step LIF (R8 verbatim — proven 37.2us) ---------
__global__ __launch_bounds__(256) void k_lif(float* __restrict__ out){
    int i = blockIdx.x * 256 + threadIdx.x;
    int d0 = (i << 2) & 127;
    float4 mn = *(const float4*)(g_mean + d0);
    float4 rs = *(const float4*)(g_rstd + d0);
    size_t base = (size_t)i << 2;

    float v0 = 0.f, v1 = 0.f, v2 = 0.f, v3 = 0.f;
    #pragma unroll
    for (int t = 0; t < 4; t++){
        float4 h = *(const float4*)(g_h + base + (size_t)t * TBND);
        float n0 = (h.x - mn.x) * rs.x;
        float n1 = (h.y - mn.y) * rs.y;
        float n2 = (h.z - mn.z) * rs.z;
        float n3 = (h.w - mn.w) * rs.w;
        v0 = v0 + (n0 - v0) * 0.5f;
        v1 = v1 + (n1 - v1) * 0.5f;
        v2 = v2 + (n2 - v2) * 0.5f;
        v3 = v3 + (n3 - v3) * 0.5f;
        float4 o;
        o.x = (v0 >= 1.0f) ? 1.0f : 0.0f;
        o.y = (v1 >= 1.0f) ? 1.0f : 0.0f;
        o.z = (v2 >= 1.0f) ? 1.0f : 0.0f;
        o.w = (v3 >= 1.0f) ? 1.0f : 0.0f;
        if (v0 >= 1.0f) v0 = 0.f;
        if (v1 >= 1.0f) v1 = 0.f;
        if (v2 >= 1.0f) v2 = 0.f;
        if (v3 >= 1.0f) v3 = 0.f;
        *(float4*)(out + base + (size_t)t * TBND) = o;
    }
}

// ---------------- launch ----------------
extern "C" void kernel_launch(void* const* d_in, const int* in_sizes, int n_in,
                              void* d_out, int out_size){
    const float* x     = (const float*)d_in[0];
    const float* W     = (const float*)d_in[1];
    const float* gamma = (const float*)d_in[2];
    const float* beta  = (const float*)d_in[3];
    float* out = (float*)d_out;

    cudaFuncSetAttribute(k_gemm, cudaFuncAttributeMaxDynamicSharedMemorySize, SM_GEMM);

    k_wt   <<<32, 256>>>(W);
    k_gemm <<<NBLK, 256, SM_GEMM>>>(x);
    k_stats<<<D_, 256>>>(gamma, beta);
    k_lif  <<<TBND / 4 / 256, 256>>>(out);
}

// round 11
// speedup vs baseline: 1.1199x; 1.0318x over previous
#include <cuda_runtime.h>
#include <cuda_bf16.h>
#include <cstdint>

// ---------------- problem constants ----------------
#define T_    4
#define NBN   65536
#define P_    63
#define D_    128
#define M_    262144
#define TBND  8388608
#define NBLK  2048              // GEMM blocks (128 rows each)

// dyn smem: A limbs [0,16K,32K), B limbs [49152, 65536, 81920).
// x raw stage reuses B area [49152, +32256). Epilogue stage reuses [0,67584).
#define SM_GEMM 98304

// ---------------- device globals ----------------
__device__ float g_h[(size_t)M_ * D_];                 // 134 MB intermediate
__device__ __align__(16) unsigned char g_wb[49152];    // 3 pre-swizzled W bf16 limb tiles
__device__ float g_psum[NBLK * D_];                    // [d][blk] transposed
__device__ float g_psq [NBLK * D_];                    // [d][blk] transposed
__device__ float g_mean[D_];
__device__ float g_rstd[D_];

// ---------------- helpers ----------------
__device__ __forceinline__ uint32_t smem_u32(const void* p){
    uint32_t a;
    asm("{ .reg .u64 t; cvta.to.shared.u64 t, %1; cvt.u32.u64 %0, t; }" : "=r"(a) : "l"(p));
    return a;
}
__device__ __forceinline__ void ldsm4(uint32_t* r, uint32_t addr){
    asm volatile("ldmatrix.sync.aligned.m8n8.x4.shared.b16 {%0,%1,%2,%3}, [%4];"
        : "=r"(r[0]), "=r"(r[1]), "=r"(r[2]), "=r"(r[3]) : "r"(addr));
}
__device__ __forceinline__ void mma16816(float* c, const uint32_t* a, const uint32_t* b){
    asm volatile("mma.sync.aligned.m16n8k16.row.col.f32.bf16.bf16.f32 "
        "{%0,%1,%2,%3}, {%4,%5,%6,%7}, {%8,%9}, {%0,%1,%2,%3};"
        : "+f"(c[0]), "+f"(c[1]), "+f"(c[2]), "+f"(c[3])
        : "r"(a[0]), "r"(a[1]), "r"(a[2]), "r"(a[3]), "r"(b[0]), "r"(b[1]));
}
// full 16-mma sweep of one A limb against one B fragment set (order == R8)
__device__ __forceinline__ void sweep(float acc[2][8][4],
                                      const uint32_t A[2][4], const uint32_t B[4][4]){
    #pragma unroll
    for (int rg = 0; rg < 2; rg++)
        #pragma unroll
        for (int j = 0; j < 4; j++){
            mma16816(acc[rg][2*j],   A[rg], &B[j][0]);
            mma16816(acc[rg][2*j+1], A[rg], &B[j][2]);
        }
}
// swizzled byte offset inside a [128 rows x 64 bf16] tile (identical to R3/R8)
__device__ __forceinline__ uint32_t sw_off(int row, int k){
    return (uint32_t)(row * 128 + ((((k >> 3) ^ row) & 7) << 4) + ((k & 7) << 1));
}

// ---------------- K0: W -> 3 pre-swizzled bf16 limb tiles (verbatim) --------
__global__ __launch_bounds__(256) void k_wt(const float* __restrict__ W){
    int idx = blockIdx.x * 256 + threadIdx.x;
    if (idx >= D_ * 64) return;
    int d = idx >> 6;
    int k = idx & 63;
    float w = (k < P_) ? W[d * P_ + k] : 0.f;
    __nv_bfloat16 w0 = __float2bfloat16(w);
    float r1 = w - __bfloat162float(w0);
    __nv_bfloat16 w1 = __float2bfloat16(r1);
    float r2 = r1 - __bfloat162float(w1);
    __nv_bfloat16 w2 = __float2bfloat16(r2);
    uint32_t off = sw_off(d, k);
    *(__nv_bfloat16*)(g_wb + off)         = w0;
    *(__nv_bfloat16*)(g_wb + 16384 + off) = w1;
    *(__nv_bfloat16*)(g_wb + 32768 + off) = w2;
}

// ---------------- K1: 6-product split-bf16 HMMA GEMM (math == R8) -----------
__global__ __launch_bounds__(256, 2) void k_gemm(const float* __restrict__ x){
    extern __shared__ __align__(1024) unsigned char smem[];
    const uint32_t sb = smem_u32(smem);
    const int tid = threadIdx.x;
    const int w   = tid >> 5;
    const int l   = tid & 31;
    const int blk = blockIdx.x;

    // --- preload B limbs into registers (LDG issued early, deep MLP) ---
    uint4 breg[12];
    {
        const uint4* gs = (const uint4*)g_wb;
        #pragma unroll
        for (int i = 0; i < 12; i++) breg[i] = gs[tid + i * 256];
    }

    // --- stage x raw: fully coalesced float4 loads into B area ---
    {
        float4* xs4 = (float4*)(smem + 49152);
        const float4* xg4 = (const float4*)(x + (size_t)blk * (128 * P_));
        #pragma unroll
        for (int i = 0; i < 8; i++){
            int idx = tid + i * 256;
            if (idx < 2016) xs4[idx] = xg4[idx];
        }
    }
    __syncthreads();

    // --- A limbs: identical split arithmetic, sourced from smem stage ---
    {
        const float* xs = (const float*)(smem + 49152);
        const int row  = tid >> 1;
        const int half = tid & 1;
        const float* xr = xs + row * P_;
        #pragma unroll
        for (int i = 0; i < 16; i++){
            int p = half * 16 + i;
            int k = p * 2;
            float v0 = xr[k];
            float v1 = (k + 1 < P_) ? xr[k + 1] : 0.f;
            uint32_t p0;
            asm("cvt.rn.bf16x2.f32 %0, %1, %2;" : "=r"(p0) : "f"(v1), "f"(v0));
            float f0 = __uint_as_float(p0 << 16);
            float f1 = __uint_as_float(p0 & 0xffff0000u);
            float r0 = v0 - f0, r1 = v1 - f1;
            uint32_t p1;
            asm("cvt.rn.bf16x2.f32 %0, %1, %2;" : "=r"(p1) : "f"(r1), "f"(r0));
            float g0 = __uint_as_float(p1 << 16);
            float g1 = __uint_as_float(p1 & 0xffff0000u);
            float s0 = r0 - g0, s1 = r1 - g1;
            uint32_t p2;
            asm("cvt.rn.bf16x2.f32 %0, %1, %2;" : "=r"(p2) : "f"(s1), "f"(s0));
            uint32_t off = (uint32_t)(row * 128
                         + ((((k >> 3) ^ row) & 7) << 4) + ((k & 7) << 1));
            *(uint32_t*)(smem + off)         = p0;
            *(uint32_t*)(smem + 16384 + off) = p1;
            *(uint32_t*)(smem + 32768 + off) = p2;
        }
    }
    __syncthreads();

    // --- B limbs: store preloaded registers (overwrites x stage) ---
    {
        uint4* bs = (uint4*)(smem + 49152);
        #pragma unroll
        for (int i = 0; i < 12; i++) bs[tid + i * 256] = breg[i];
    }
    __syncthreads();

    // warp tile: 32 rows x 64 cols. 8 warps = 4 row-groups x 2 col-groups.
    const int rowg = (w >> 1) * 32;
    const int colg = (w & 1) * 64;
    const int a_r  = l & 15;
    const int a_kb = l >> 4;
    const int b_rl = (l & 7) + ((l >> 4) & 1) * 8;
    const int b_kb = (l >> 3) & 1;

    // per-lane base addresses; per-ks address = base ^ (ks<<5)
    uint32_t aBase[2];
    #pragma unroll
    for (int rg = 0; rg < 2; rg++){
        int row = rowg + rg * 16 + a_r;
        aBase[rg] = sb + (uint32_t)row * 128
                  + (uint32_t)(((a_kb ^ (row & 7)) & 7) << 4);
    }
    uint32_t bBase[4];
    #pragma unroll
    for (int j = 0; j < 4; j++){
        int rowd = colg + j * 16 + b_rl;
        bBase[j] = sb + 49152 + (uint32_t)rowd * 128
                 + (uint32_t)(((b_kb ^ (rowd & 7)) & 7) << 4);
    }

    float acc[2][8][4];
    #pragma unroll
    for (int i = 0; i < 2; i++)
        #pragma unroll
        for (int j = 0; j < 8; j++)
            #pragma unroll
            for (int e = 0; e < 4; e++) acc[i][j][e] = 0.f;

    uint32_t A0[2][4], A1[2][4], A2[2][4], Bx[4][4], By[4][4];

    // per-acc product order: (0,0),(1,0),(2,0),(0,1),(1,1),(0,2); ks ascending
    #pragma unroll
    for (int ks = 0; ks < 4; ks++){
        const uint32_t kx = (uint32_t)(ks << 5);
        #pragma unroll
        for (int rg = 0; rg < 2; rg++){
            uint32_t a = aBase[rg] ^ kx;
            ldsm4(A0[rg], a);
            ldsm4(A1[rg], a + 16384);
            ldsm4(A2[rg], a + 32768);
        }
        #pragma unroll
        for (int j = 0; j < 4; j++) ldsm4(Bx[j], bBase[j] ^ kx);   // B limb 0

        // sweep A0 x B0 (rg0) with B1 prefetch interleaved into By
        mma16816(acc[0][0], A0[0], &Bx[0][0]); mma16816(acc[0][1], A0[0], &Bx[0][2]);
        ldsm4(By[0], (bBase[0] ^ kx) + 16384);
        mma16816(acc[0][2], A0[0], &Bx[1][0]); mma16816(acc[0][3], A0[0], &Bx[1][2]);
        ldsm4(By[1], (bBase[1] ^ kx) + 16384);
        mma16816(acc[0][4], A0[0], &Bx[2][0]); mma16816(acc[0][5], A0[0], &Bx[2][2]);
        ldsm4(By[2], (bBase[2] ^ kx) + 16384);
        mma16816(acc[0][6], A0[0], &Bx[3][0]); mma16816(acc[0][7], A0[0], &Bx[3][2]);
        ldsm4(By[3], (bBase[3] ^ kx) + 16384);
        // rg1 of A0 x B0
        #pragma unroll
        for (int j = 0; j < 4; j++){
            mma16816(acc[1][2*j],   A0[1], &Bx[j][0]);
            mma16816(acc[1][2*j+1], A0[1], &Bx[j][2]);
        }
        sweep(acc, A1, Bx);            // (1,0)
        sweep(acc, A2, Bx);            // (2,0) -- last use of B0 buffer
        #pragma unroll
        for (int j = 0; j < 4; j++) ldsm4(Bx[j], (bBase[j] ^ kx) + 32768);  // B limb 2
        sweep(acc, A0, By);            // (0,1)
        sweep(acc, A1, By);            // (1,1)
        sweep(acc, A0, Bx);            // (0,2)
    }

    // ---- epilogue: stage (verbatim R8), coalesced h write, stats ----
    __syncthreads();
    float* stg = (float*)smem;                 // [128][132]
    #pragma unroll
    for (int rg = 0; rg < 2; rg++){
        int rr = rowg + rg * 16 + (l >> 2);
        #pragma unroll
        for (int jh = 0; jh < 8; jh++){
            int col = colg + jh * 8 + (l & 3) * 2;
            *(float2*)(stg + rr * 132 + col)       = make_float2(acc[rg][jh][0], acc[rg][jh][1]);
            *(float2*)(stg + (rr + 8) * 132 + col) = make_float2(acc[rg][jh][2], acc[rg][jh][3]);
        }
    }
    __syncthreads();

    float* hg = g_h + (size_t)blk * (128 * 128);
    #pragma unroll
    for (int j = 0; j < 16; j++){
        int idx = tid + j * 256;
        int row = idx >> 5;
        int c4  = idx & 31;
        float4 v = *(const float4*)(stg + row * 132 + c4 * 4);
        *(float4*)(hg + row * 128 + c4 * 4) = v;
    }
    // same summation order as R8; only the memory layout is transposed
    if (tid < 128){
        float s = 0.f;
        #pragma unroll 8
        for (int r = 0; r < 128; r++) s += stg[r * 132 + tid];
        g_psum[tid * NBLK + blk] = s;
    } else {
        int d = tid - 128;
        float q = 0.f;
        #pragma unroll 8
        for (int r = 0; r < 128; r++){ float v = stg[r * 132 + d]; q += v * v; }
        g_psq[d * NBLK + blk] = q;
    }
}

// ---------------- K2: finalize stats (same order, coalesced reads) ----------
__global__ __launch_bounds__(256) void k_stats(const float* __restrict__ gamma,
                                               const float* __restrict__ beta){
    __shared__ double ss[256];
    __shared__ double sq[256];
    const int d = blockIdx.x;
    const int t = threadIdx.x;
    double s = 0.0, q = 0.0;
    for (int b = t; b < NBLK; b += 256){
        s += (double)g_psum[d * NBLK + b];
        q += (double)g_psq [d * NBLK + b];
    }
    ss[t] = s; sq[t] = q;
    __syncthreads();
    for (int o = 128; o > 0; o >>= 1){
        if (t < o){ ss[t] += ss[t + o]; sq[t] += sq[t + o]; }
        __syncthreads();
    }
    if (t == 0){
        double mean = ss[0] / (double)M_;
        double ex2  = sq[0] / (double)M_;
        float meanf = (float)mean;
        float varf  = (float)(ex2 - mean * mean);
        float rstd  = (float)(1.0 / sqrt((double)(varf + 1e-5f)));
        float gm = gamma[d], bt = beta[d];
        float rs = rstd * gm;
        float mn = (rs != 0.f) ? (meanf - bt / rs) : meanf;
        g_mean[d] = mn;
        g_rstd[d] = rs;
    }
}

// ---------------- K3: BN + 4-step LIF (R8 math, streaming cache hints) ------
__global__ __launch_bounds__(256) void k_lif(float* __restrict__ out){
    int i = blockIdx.x * 256 + threadIdx.x;
    int d0 = (i << 2) & 127;
    float4 mn = *(const float4*)(g_mean + d0);
    float4 rs = *(const float4*)(g_rstd + d0);
    size_t base = (size_t)i << 2;

    float v0 = 0.f, v1 = 0.f, v2 = 0.f, v3 = 0.f;
    #pragma unroll
    for (int t = 0; t < 4; t++){
        float4 h = __ldcs((const float4*)(g_h + base + (size_t)t * TBND));
        float n0 = (h.x - mn.x) * rs.x;
        float n1 = (h.y - mn.y) * rs.y;
        float n2 = (h.z - mn.z) * rs.z;
        float n3 = (h.w - mn.w) * rs.w;
        v0 = v0 + (n0 - v0) * 0.5f;
        v1 = v1 + (n1 - v1) * 0.5f;
        v2 = v2 + (n2 - v2) * 0.5f;
        v3 = v3 + (n3 - v3) * 0.5f;
        float4 o;
        o.x = (v0 >= 1.0f) ? 1.0f : 0.0f;
        o.y = (v1 >= 1.0f) ? 1.0f : 0.0f;
        o.z = (v2 >= 1.0f) ? 1.0f : 0.0f;
        o.w = (v3 >= 1.0f) ? 1.0f : 0.0f;
        if (v0 >= 1.0f) v0 = 0.f;
        if (v1 >= 1.0f) v1 = 0.f;
        if (v2 >= 1.0f) v2 = 0.f;
        if (v3 >= 1.0f) v3 = 0.f;
        __stcs((float4*)(out + base + (size_t)t * TBND), o);
    }
}

// ---------------- launch ----------------
extern "C" void kernel_launch(void* const* d_in, const int* in_sizes, int n_in,
                              void* d_out, int out_size){
    const float* x     = (const float*)d_in[0];
    const float* W     = (const float*)d_in[1];
    const float* gamma = (const float*)d_in[2];
    const float* beta  = (const float*)d_in[3];
    float* out = (float*)d_out;

    cudaFuncSetAttribute(k_gemm, cudaFuncAttributeMaxDynamicSharedMemorySize, SM_GEMM);

    k_wt   <<<32, 256>>>(W);
    k_gemm <<<NBLK, 256, SM_GEMM>>>(x);
    k_stats<<<D_, 256>>>(gamma, beta);
    k_lif  <<<TBND / 4 / 256, 256>>>(out);
}